// round 16
// baseline (speedup 1.0000x reference)
#include <cuda_runtime.h>
#include <cuda_bf16.h>
#include <cuda_fp16.h>
#include <math.h>
#include <stdint.h>

#define N_NODES 100000
#define N_EDGES 1600000
#define NBLK    ((N_NODES + 127) / 128)      // 782
#define PAD 136   // 16-bit elems per SMEM row: 272B stride -> conflict-free ldmatrix

#define CNT_B   ((N_EDGES + 1023) / 1024)    // 1563 count blocks (4 edges/thread)
#define PREP_B  ((3 * 16384 + 8192 + 255) / 256)  // 224
#define SB_BLOCKS ((N_NODES + 255) / 256)    // 391 scan/build blocks

// ---------------- scratch (static device globals; no allocation) ----------------
__device__ __half g_Uh[(size_t)N_NODES * 128]; // u = (h @ W) (raw for L1, scaled L2/3), fp16
__device__ __half g_Hh[(size_t)N_NODES * 128]; // layer activations, fp16
__device__ __half g_Whf[3 * 16384];            // W1..W3 fp16 images [n][k]
__device__ __nv_bfloat16 g_Wbf[16384];         // Wout bf16 hi/lo images [n][k]
__device__ int   g_srcSorted[N_EDGES];
__device__ int   g_cnt[N_NODES];               // ZEROED at module load; self-restoring
__device__ int   g_rowstart[N_NODES + 1];
__device__ int   g_cursor[N_NODES];
__device__ float g_invs[N_NODES];
__device__ int   g_is64;
__device__ volatile unsigned g_state[SB_BLOCKS];  // lookback: status<<30 | value
__device__ unsigned g_arrive;                     // grid barrier (reset by k0)

#define WO_HI 0
#define WO_LO 8192

// ---------------- mma helpers ----------------
__device__ __forceinline__ void ldsm4(uint32_t* r, const void* p) {
    uint32_t a = (uint32_t)__cvta_generic_to_shared(p);
    asm volatile("ldmatrix.sync.aligned.m8n8.x4.shared.b16 {%0,%1,%2,%3}, [%4];"
                 : "=r"(r[0]), "=r"(r[1]), "=r"(r[2]), "=r"(r[3]) : "r"(a));
}

__device__ __forceinline__ void mma_bf16(float* c, const uint32_t* a, const uint32_t* b) {
    asm volatile(
        "mma.sync.aligned.m16n8k16.row.col.f32.bf16.bf16.f32 "
        "{%0,%1,%2,%3}, {%4,%5,%6,%7}, {%8,%9}, {%0,%1,%2,%3};"
        : "+f"(c[0]), "+f"(c[1]), "+f"(c[2]), "+f"(c[3])
        : "r"(a[0]), "r"(a[1]), "r"(a[2]), "r"(a[3]), "r"(b[0]), "r"(b[1]));
}

__device__ __forceinline__ void mma_fp16(float* c, const uint32_t* a, const uint32_t* b) {
    asm volatile(
        "mma.sync.aligned.m16n8k16.row.col.f32.f16.f16.f32 "
        "{%0,%1,%2,%3}, {%4,%5,%6,%7}, {%8,%9}, {%0,%1,%2,%3};"
        : "+f"(c[0]), "+f"(c[1]), "+f"(c[2]), "+f"(c[3])
        : "r"(a[0]), "r"(a[1]), "r"(a[2]), "r"(a[3]), "r"(b[0]), "r"(b[1]));
}

__device__ __forceinline__ int load_idx(const void* ei, long long pos) {
    if (g_is64) return (int)((const long long*)ei)[pos];
    return ((const int*)ei)[pos];
}

// ---------------- K0: weight-image prep + dtype probe + barrier/state reset ----------------
__global__ __launch_bounds__(256) void k0_prep(
    const int* __restrict__ ei_raw,
    const float* __restrict__ W1, const float* __restrict__ W2,
    const float* __restrict__ W3, const float* __restrict__ Wo)
{
    int bid = blockIdx.x;
    if (bid < PREP_B) {
        int e = bid * 256 + threadIdx.x;
        if (e < 3 * 16384) {
            int layer = e >> 14;
            int elem = e & 16383;
            int k = elem >> 7, n = elem & 127;
            const float* W = (layer == 0) ? W1 : ((layer == 1) ? W2 : W3);
            g_Whf[layer * 16384 + n * 128 + k] = __float2half_rn(W[elem]);
        } else {
            int elem = e - 3 * 16384;       // 0..8191
            int k = elem >> 6, n = elem & 63;
            float v = Wo[elem];
            __nv_bfloat16 hb = __float2bfloat16(v);
            __nv_bfloat16 lb = __float2bfloat16(v - __bfloat162float(hb));
            g_Wbf[WO_HI + n * 128 + k] = hb;
            g_Wbf[WO_LO + n * 128 + k] = lb;
        }
    } else {
        // reset lookback state + barrier; dtype probe
        int t = threadIdx.x;
        if (t < SB_BLOCKS) g_state[t] = 0u;
        if (t + 256 < SB_BLOCKS) g_state[t + 256] = 0u;
        if (t == 0) g_arrive = 0u;
        if (t < 32) {
            int lane = t;
            int bad = 0;
            for (int i = lane; i < 1024; i += 32)
                bad |= (ei_raw[2 * i + 1] != 0);
            unsigned m = __ballot_sync(0xffffffffu, bad);
            if (lane == 0) g_is64 = (m == 0);
        }
    }
}

// ---------------- GEMM core (device fn): D[128,128] tile = X @ W, fp16 mma ----------------
template <bool XEXT, bool SCALE>
__device__ __forceinline__ void gemm_core(int bid, const float* __restrict__ Xext,
                                          int w_off, __half* smh)
{
    __half* Af = smh;                 // [128][PAD]
    __half* Bf = Af + 128 * PAD;      // [128][PAD]

    int tid = threadIdx.x;
    int lane = tid & 31, warp = tid >> 5;
    int r0 = bid * 128;

    if (XEXT) {
        #pragma unroll
        for (int i = 0; i < 16; i++) {
            int j = tid + i * 256;
            int row = j >> 5, c4 = (j & 31) << 2;
            float4 v = make_float4(0.f, 0.f, 0.f, 0.f);
            if (r0 + row < N_NODES)
                v = *(const float4*)&Xext[(size_t)(r0 + row) * 128 + c4];
            __half2 h0 = __floats2half2_rn(v.x, v.y);
            __half2 h1 = __floats2half2_rn(v.z, v.w);
            *(uint2*)&Af[row * PAD + c4] =
                make_uint2(*(uint32_t*)&h0, *(uint32_t*)&h1);
        }
    } else {
        #pragma unroll
        for (int i = 0; i < 8; i++) {
            int j = tid + i * 256;
            int row = j >> 4, q = j & 15;
            uint4 v = make_uint4(0u, 0u, 0u, 0u);
            if (r0 + row < N_NODES)
                v = *(const uint4*)&g_Hh[(size_t)(r0 + row) * 128 + q * 8];
            *(uint4*)&Af[row * PAD + q * 8] = v;
        }
    }
    #pragma unroll
    for (int i = 0; i < 8; i++) {
        int j = tid + i * 256;
        int row = j >> 4, q = j & 15;
        *(uint4*)&Bf[row * PAD + q * 8] = *(const uint4*)&g_Whf[w_off + row * 128 + q * 8];
    }
    __syncthreads();

    int wm = (warp & 3) * 32;
    int wn = (warp >> 2) * 64;

    float acc[2][8][4];
    #pragma unroll
    for (int mt = 0; mt < 2; mt++)
        #pragma unroll
        for (int nt = 0; nt < 8; nt++)
            #pragma unroll
            for (int q = 0; q < 4; q++) acc[mt][nt][q] = 0.f;

    int arow = lane & 15, acol = (lane >> 4) << 3;
    int brow = (lane & 7) + ((lane >> 4) << 3), bcol = ((lane >> 3) & 1) << 3;

    #pragma unroll
    for (int kk = 0; kk < 128; kk += 16) {
        uint32_t af[2][4];
        ldsm4(af[0], Af + (wm + arow) * PAD + kk + acol);
        ldsm4(af[1], Af + (wm + 16 + arow) * PAD + kk + acol);

        uint32_t bf[8][2];
        #pragma unroll
        for (int p = 0; p < 4; p++) {
            uint32_t t[4];
            ldsm4(t, Bf + (wn + p * 16 + brow) * PAD + kk + bcol);
            bf[2*p][0] = t[0]; bf[2*p][1] = t[1];
            bf[2*p+1][0] = t[2]; bf[2*p+1][1] = t[3];
        }

        #pragma unroll
        for (int mt = 0; mt < 2; mt++)
            #pragma unroll
            for (int nt = 0; nt < 8; nt++)
                mma_fp16(acc[mt][nt], af[mt], bf[nt]);
    }

    #pragma unroll
    for (int mt = 0; mt < 2; mt++) {
        int r1 = r0 + wm + mt * 16 + (lane >> 2);
        int r2 = r1 + 8;
        float s1 = 1.f, s2 = 1.f;
        if (SCALE) {
            s1 = (r1 < N_NODES) ? g_invs[r1] : 0.f;
            s2 = (r2 < N_NODES) ? g_invs[r2] : 0.f;
        }
        #pragma unroll
        for (int nt = 0; nt < 8; nt++) {
            int col = wn + nt * 8 + ((lane & 3) << 1);
            if (r1 < N_NODES)
                *(__half2*)&g_Uh[(size_t)r1 * 128 + col] =
                    __floats2half2_rn(acc[mt][nt][0] * s1, acc[mt][nt][1] * s1);
            if (r2 < N_NODES)
                *(__half2*)&g_Uh[(size_t)r2 * 128 + col] =
                    __floats2half2_rn(acc[mt][nt][2] * s2, acc[mt][nt][3] * s2);
        }
    }
}

// ---------------- K1: degree count + layer-1 GEMM (raw, unscaled) fused ----------------
__global__ __launch_bounds__(256) void k1_count_gemm1(const void* __restrict__ ei,
                                                      const float* __restrict__ x)
{
    extern __shared__ __align__(16) __half smh[];
    int bid = blockIdx.x;
    if (bid < CNT_B) {
        int base = bid * 1024 + threadIdx.x;
        #pragma unroll
        for (int i = 0; i < 4; i++) {
            int e = base + i * 256;
            if (e < N_EDGES) {
                int d = load_idx(ei, (long long)N_EDGES + e);
                if (d >= 0 && d < N_NODES) atomicAdd(&g_cnt[d], 1);
            }
        }
    } else {
        gemm_core<true, false>(bid - CNT_B, x, 0, smh);
    }
}

// ---------------- standalone GEMM (layers 2,3) ----------------
__global__ __launch_bounds__(256) void gemm_fp16_k(int w_off) {
    extern __shared__ __align__(16) __half smh[];
    gemm_core<false, true>(blockIdx.x, nullptr, w_off, smh);
}

// ---------------- fused scan (decoupled lookback) + grid barrier + CSR build ----------------
// 391 blocks x 256 threads; all co-resident (>=8 CTAs/SM capacity vs 2.7/SM needed).
__global__ __launch_bounds__(256) void scan_build_kernel(const void* __restrict__ ei) {
    __shared__ int wsum[8];
    __shared__ int s_excl;
    int bid = blockIdx.x;
    int tid = threadIdx.x, lane = tid & 31, wid = tid >> 5;
    int i = bid * 256 + tid;

    // ---- phase A: scan ----
    int v = (i < N_NODES) ? g_cnt[i] : 0;
    if (i < N_NODES) g_cnt[i] = 0;          // self-restoring reset for next call

    int x = v;
    #pragma unroll
    for (int off = 1; off < 32; off <<= 1) {
        int y = __shfl_up_sync(0xffffffffu, x, off);
        if (lane >= off) x += y;
    }
    if (lane == 31) wsum[wid] = x;
    __syncthreads();
    if (wid == 0 && lane < 8) {
        int w = wsum[lane];
        #pragma unroll
        for (int off = 1; off < 8; off <<= 1) {
            int y = __shfl_up_sync(0xffu, w, off);
            if (lane >= off) w += y;
        }
        wsum[lane] = w;
    }
    __syncthreads();
    int incl = x + (wid ? wsum[wid - 1] : 0);      // block-inclusive prefix
    int btotal = wsum[7];

    if (tid == 0) {
        unsigned excl;
        if (bid == 0) {
            excl = 0;
            g_state[0] = (2u << 30) | (unsigned)btotal;
        } else {
            g_state[bid] = (1u << 30) | (unsigned)btotal;
            unsigned run = 0;
            int pred = bid - 1;
            while (true) {
                unsigned s = g_state[pred];
                unsigned tag = s >> 30;
                if (tag == 0u) continue;
                run += s & 0x3FFFFFFFu;
                if (tag == 2u) break;
                pred--;
            }
            excl = run;
            g_state[bid] = (2u << 30) | (run + (unsigned)btotal);
        }
        s_excl = (int)excl;
    }
    __syncthreads();
    int excl = s_excl;

    if (i < N_NODES) {
        int rs = excl + incl - v;                   // exclusive global prefix
        g_rowstart[i] = rs;
        g_cursor[i] = rs;
        g_invs[i] = rsqrtf((float)(v + 1));
    }
    if (bid == SB_BLOCKS - 1 && tid == 0)
        g_rowstart[N_NODES] = excl + btotal;

    // ---- grid barrier ----
    __syncthreads();
    if (tid == 0) {
        __threadfence();
        atomicAdd(&g_arrive, 1u);
        while (*(volatile unsigned*)&g_arrive < (unsigned)SB_BLOCKS) {}
    }
    __syncthreads();

    // ---- phase B: CSR build (grid-stride) ----
    for (int e = bid * 256 + tid; e < N_EDGES; e += SB_BLOCKS * 256) {
        int s = load_idx(ei, e);
        int d = load_idx(ei, (long long)N_EDGES + e);
        if (s >= 0 && s < N_NODES && d >= 0 && d < N_NODES) {
            int p = atomicAdd(&g_cursor[d], 1);
            if (p >= 0 && p < N_EDGES) g_srcSorted[p] = s;
        }
    }
}

// ---------------- output GEMM: bf16 split 3-pass (N=64), fp32 out + bias ----------------
__global__ __launch_bounds__(256) void gemm_out(const float* __restrict__ bias,
                                                float* __restrict__ Yout) {
    constexpr int N = 64;
    extern __shared__ __align__(16) __nv_bfloat16 sm[];
    __nv_bfloat16* Ah = sm;                         // [128][PAD]
    __nv_bfloat16* Al = Ah + 128 * PAD;
    __nv_bfloat16* Bh = Al + 128 * PAD;             // [N][PAD]
    __nv_bfloat16* Bl = Bh + N * PAD;

    int tid = threadIdx.x;
    int lane = tid & 31, warp = tid >> 5;
    int r0 = blockIdx.x * 128;

    #pragma unroll
    for (int i = 0; i < 16; i++) {
        int j = tid + i * 256;
        int row = j >> 5, c4 = (j & 31) << 2;
        uint2 hv = make_uint2(0u, 0u);
        if (r0 + row < N_NODES)
            hv = *(const uint2*)&g_Hh[(size_t)(r0 + row) * 128 + c4];
        const __half* hp = (const __half*)&hv;
        uint32_t h[4], l[4];
        #pragma unroll
        for (int q = 0; q < 4; q++) {
            float f = __half2float(hp[q]);
            __nv_bfloat16 hb = __float2bfloat16(f);
            h[q] = (uint32_t)__bfloat16_as_ushort(hb);
            l[q] = (uint32_t)__bfloat16_as_ushort(
                       __float2bfloat16(f - __bfloat162float(hb)));
        }
        *(uint2*)&Ah[row * PAD + c4] = make_uint2(h[0] | (h[1] << 16), h[2] | (h[3] << 16));
        *(uint2*)&Al[row * PAD + c4] = make_uint2(l[0] | (l[1] << 16), l[2] | (l[3] << 16));
    }
    #pragma unroll
    for (int i = 0; i < N * 16 / 256; i++) {
        int j = tid + i * 256;
        int row = j >> 4, q = j & 15;
        *(uint4*)&Bh[row * PAD + q * 8] = *(const uint4*)&g_Wbf[WO_HI + row * 128 + q * 8];
        *(uint4*)&Bl[row * PAD + q * 8] = *(const uint4*)&g_Wbf[WO_LO + row * 128 + q * 8];
    }
    __syncthreads();

    constexpr int NT = N / 16;   // 4
    int wm = (warp & 3) * 32;
    int wn = (warp >> 2) * (N / 2);

    float acc[2][NT][4];
    #pragma unroll
    for (int mt = 0; mt < 2; mt++)
        #pragma unroll
        for (int nt = 0; nt < NT; nt++)
            #pragma unroll
            for (int q = 0; q < 4; q++) acc[mt][nt][q] = 0.f;

    int arow = lane & 15, acol = (lane >> 4) << 3;
    int brow = (lane & 7) + ((lane >> 4) << 3), bcol = ((lane >> 3) & 1) << 3;

    #pragma unroll
    for (int kk = 0; kk < 128; kk += 16) {
        uint32_t ah[2][4], al[2][4];
        ldsm4(ah[0], Ah + (wm + arow) * PAD + kk + acol);
        ldsm4(ah[1], Ah + (wm + 16 + arow) * PAD + kk + acol);
        ldsm4(al[0], Al + (wm + arow) * PAD + kk + acol);
        ldsm4(al[1], Al + (wm + 16 + arow) * PAD + kk + acol);

        uint32_t bh[NT][2], bl[NT][2];
        #pragma unroll
        for (int p = 0; p < NT / 2; p++) {
            uint32_t t[4];
            ldsm4(t, Bh + (wn + p * 16 + brow) * PAD + kk + bcol);
            bh[2*p][0] = t[0]; bh[2*p][1] = t[1];
            bh[2*p+1][0] = t[2]; bh[2*p+1][1] = t[3];
            ldsm4(t, Bl + (wn + p * 16 + brow) * PAD + kk + bcol);
            bl[2*p][0] = t[0]; bl[2*p][1] = t[1];
            bl[2*p+1][0] = t[2]; bl[2*p+1][1] = t[3];
        }

        #pragma unroll
        for (int mt = 0; mt < 2; mt++)
            #pragma unroll
            for (int nt = 0; nt < NT; nt++) {
                mma_bf16(acc[mt][nt], ah[mt], bh[nt]);
                mma_bf16(acc[mt][nt], ah[mt], bl[nt]);
                mma_bf16(acc[mt][nt], al[mt], bh[nt]);
            }
    }

    #pragma unroll
    for (int mt = 0; mt < 2; mt++) {
        int r1 = r0 + wm + mt * 16 + (lane >> 2);
        int r2 = r1 + 8;
        #pragma unroll
        for (int nt = 0; nt < NT; nt++) {
            int col = wn + nt * 8 + ((lane & 3) << 1);
            float bx = bias[col], by = bias[col + 1];
            if (r1 < N_NODES)
                *(float2*)&Yout[(size_t)r1 * N + col] =
                    make_float2(acc[mt][nt][0] + bx, acc[mt][nt][1] + by);
            if (r2 < N_NODES)
                *(float2*)&Yout[(size_t)r2 * N + col] =
                    make_float2(acc[mt][nt][2] + bx, acc[mt][nt][3] + by);
        }
    }
}

// ---------------- aggregation: warp per node, 2 halves x 2 edges in flight ----------------
template <bool RELU, bool SRCSCALE>
__global__ __launch_bounds__(256) void agg_kernel(const float* __restrict__ bias) {
    int gw = (blockIdx.x * 256 + threadIdx.x) >> 5;
    int lane = threadIdx.x & 31;
    if (gw >= N_NODES) return;

    int half_id = lane >> 4;          // 0 or 1
    int sub = lane & 15;              // position within row (8 halves each)

    const uint4* Up = (const uint4*)g_Uh;   // row = 16 uint4

    float acc[8];
    #pragma unroll
    for (int q = 0; q < 8; q++) acc[q] = 0.f;

    // self-loop (half 0 only, counted once)
    if (half_id == 0) {
        float sc = SRCSCALE ? g_invs[gw] : 1.f;
        uint4 w = Up[(size_t)gw * 16 + sub];
        const __half2* hp = (const __half2*)&w;
        #pragma unroll
        for (int q = 0; q < 4; q++) {
            float2 p = __half22float2(hp[q]);
            acc[2*q]   = fmaf(sc, p.x, acc[2*q]);
            acc[2*q+1] = fmaf(sc, p.y, acc[2*q+1]);
        }
    }

    int beg = g_rowstart[gw];
    int end = g_rowstart[gw + 1];

    int j = beg + half_id;
    for (; j + 2 < end; j += 4) {
        int s0 = g_srcSorted[j];
        int s1 = g_srcSorted[j + 2];
        float c0 = SRCSCALE ? g_invs[s0] : 1.f;
        float c1 = SRCSCALE ? g_invs[s1] : 1.f;
        uint4 w0 = Up[(size_t)s0 * 16 + sub];
        uint4 w1 = Up[(size_t)s1 * 16 + sub];
        const __half2* h0 = (const __half2*)&w0;
        const __half2* h1 = (const __half2*)&w1;
        #pragma unroll
        for (int q = 0; q < 4; q++) {
            float2 p0 = __half22float2(h0[q]);
            float2 p1 = __half22float2(h1[q]);
            acc[2*q]   = fmaf(c0, p0.x, fmaf(c1, p1.x, acc[2*q]));
            acc[2*q+1] = fmaf(c0, p0.y, fmaf(c1, p1.y, acc[2*q+1]));
        }
    }
    for (; j < end; j += 2) {
        int s = g_srcSorted[j];
        float sc = SRCSCALE ? g_invs[s] : 1.f;
        uint4 w = Up[(size_t)s * 16 + sub];
        const __half2* hp = (const __half2*)&w;
        #pragma unroll
        for (int q = 0; q < 4; q++) {
            float2 p = __half22float2(hp[q]);
            acc[2*q]   = fmaf(sc, p.x, acc[2*q]);
            acc[2*q+1] = fmaf(sc, p.y, acc[2*q+1]);
        }
    }

    // combine the two halves
    #pragma unroll
    for (int q = 0; q < 8; q++)
        acc[q] += __shfl_xor_sync(0xffffffffu, acc[q], 16);

    if (half_id == 0) {
        float is = g_invs[gw];
        float4 b0 = ((const float4*)bias)[sub * 2];
        float4 b1 = ((const float4*)bias)[sub * 2 + 1];
        float o[8];
        o[0] = is * acc[0] + b0.x;
        o[1] = is * acc[1] + b0.y;
        o[2] = is * acc[2] + b0.z;
        o[3] = is * acc[3] + b0.w;
        o[4] = is * acc[4] + b1.x;
        o[5] = is * acc[5] + b1.y;
        o[6] = is * acc[6] + b1.z;
        o[7] = is * acc[7] + b1.w;
        if (RELU) {
            #pragma unroll
            for (int q = 0; q < 8; q++) o[q] = fmaxf(o[q], 0.f);
        }
        __half2 h0 = __floats2half2_rn(o[0], o[1]);
        __half2 h1 = __floats2half2_rn(o[2], o[3]);
        __half2 h2 = __floats2half2_rn(o[4], o[5]);
        __half2 h3 = __floats2half2_rn(o[6], o[7]);
        uint4 w;
        w.x = *(uint32_t*)&h0;
        w.y = *(uint32_t*)&h1;
        w.z = *(uint32_t*)&h2;
        w.w = *(uint32_t*)&h3;
        *(uint4*)&g_Hh[(size_t)gw * 128 + sub * 8] = w;
    }
}

// ---------------- launch ----------------
extern "C" void kernel_launch(void* const* d_in, const int* in_sizes, int n_in,
                              void* d_out, int out_size)
{
    const float* x  = (const float*)d_in[0];
    const void*  ei = d_in[1];
    const float* W1 = (const float*)d_in[2];
    const float* b1 = (const float*)d_in[3];
    const float* W2 = (const float*)d_in[4];
    const float* b2 = (const float*)d_in[5];
    const float* W3 = (const float*)d_in[6];
    const float* b3 = (const float*)d_in[7];
    const float* Wo = (const float*)d_in[8];
    const float* bo = (const float*)d_in[9];
    float* out = (float*)d_out;

    const int SMEM_F  = 2 * 128 * PAD * 2;                    // 69632 B
    const int SMEM64  = (2 * 128 * PAD + 2 * 64 * PAD) * 2;   // 104448 B
    cudaFuncSetAttribute(k1_count_gemm1,
                         cudaFuncAttributeMaxDynamicSharedMemorySize, SMEM_F);
    cudaFuncSetAttribute(gemm_fp16_k,
                         cudaFuncAttributeMaxDynamicSharedMemorySize, SMEM_F);
    cudaFuncSetAttribute(gemm_out,
                         cudaFuncAttributeMaxDynamicSharedMemorySize, SMEM64);

    const int AB = (N_NODES + 7) / 8;

    // K0: weight images + dtype probe + barrier/state reset
    k0_prep<<<PREP_B + 1, 256>>>((const int*)ei, W1, W2, W3, Wo);
    // K1: degree count + layer-1 GEMM (raw XW, fp16)
    k1_count_gemm1<<<CNT_B + NBLK, 256, SMEM_F>>>(ei, x);
    // fused CSR scan + build (persistent, grid barrier)
    scan_build_kernel<<<SB_BLOCKS, 256>>>(ei);

    // layer 1 aggregation (applies invs[src] per edge)
    agg_kernel<true, true><<<AB, 256>>>(b1);
    // layer 2
    gemm_fp16_k<<<NBLK, 256, SMEM_F>>>(16384);
    agg_kernel<true, false><<<AB, 256>>>(b2);
    // layer 3 (no relu)
    gemm_fp16_k<<<NBLK, 256, SMEM_F>>>(32768);
    agg_kernel<false, false><<<AB, 256>>>(b3);
    // output projection (bf16 3-pass, fp32 out)
    gemm_out<<<NBLK, 256, SMEM64>>>(bo, out);
}